// round 1
// baseline (speedup 1.0000x reference)
#include <cuda_runtime.h>
#include <math.h>

// out_b = p(x_b) . S[k] + beta * x_b[k] + v0[k]
// p(x) = (x0^2, x1^2, x2^2, x0x1, x0x2, x1x2)
struct Consts {
    float S[3][6];   // 18
    float beta;      // 1   (index 18 when viewed flat)
    float v0[3];     // 3   (indices 19..21)
};
__device__ Consts g_c;

__global__ void setup_kernel(const float* __restrict__ t_p,
                             const float* __restrict__ R,
                             const float* __restrict__ m,
                             const float* __restrict__ Wl1, const float* __restrict__ Wd1,
                             const float* __restrict__ Wl2, const float* __restrict__ Wd2,
                             const float* __restrict__ Wl3, const float* __restrict__ Wd3,
                             const float* __restrict__ Wl4, const float* __restrict__ Wd4,
                             const float* __restrict__ Wb1_lin,
                             const float* __restrict__ Wb1_d1, const float* __restrict__ Wb1_d2,
                             const float* __restrict__ Wb2_lin,
                             const float* __restrict__ Wb2_d1, const float* __restrict__ Wb2_d2,
                             const float* __restrict__ Wout)
{
    if (threadIdx.x != 0 || blockIdx.x != 0) return;

    const int F = 20;

    // mm[f][k] = (R @ m).T : sum_j R[k][j] * m[j][f]
    float mm[20][3];
    for (int f = 0; f < F; f++)
        for (int k = 0; k < 3; k++) {
            float s = 0.f;
            for (int j = 0; j < 3; j++) s += R[k * 3 + j] * m[j * F + f];
            mm[f][k] = s;
        }

    // map_m for the 4 (Wl, Wd) pairs -> M[i] = m_i m_i^T
    float M[4][3][3];
    const float* Wls[4] = {Wl1, Wl2, Wl3, Wl4};
    const float* Wds[4] = {Wd1, Wd2, Wd3, Wd4};
    for (int i = 0; i < 4; i++) {
        float y0[3][3], d[3][3], o[3][3];
        // y0 = Wl @ mm   (3x20 @ 20x3)
        for (int a = 0; a < 3; a++)
            for (int k = 0; k < 3; k++) {
                float s = 0.f;
                for (int f = 0; f < F; f++) s += Wls[i][a * F + f] * mm[f][k];
                y0[a][k] = s;
            }
        // d = Wd @ y0
        for (int p = 0; p < 3; p++)
            for (int k = 0; k < 3; k++) {
                float s = 0.f;
                for (int a = 0; a < 3; a++) s += Wds[i][p * 3 + a] * y0[a][k];
                d[p][k] = s;
            }
        // KillingRelu per channel f
        for (int f = 0; f < 3; f++) {
            float xd = 0.f, dd = 0.f;
            for (int k = 0; k < 3; k++) { xd += y0[f][k] * d[f][k]; dd += d[f][k] * d[f][k]; }
            float kf_xd = -2.f * xd;
            float kf_dd = -2.f * dd;
            float denom = fminf(kf_dd, -1e-12f);
            float coef  = (kf_xd < 0.f) ? 0.f : (kf_xd / denom);
            for (int k = 0; k < 3; k++) o[f][k] = y0[f][k] - coef * d[f][k];
        }
        // M[k][k2] = sum_f o[f][k] * o[f][k2]   (m_i = o^T, M = m_i m_i^T)
        for (int k = 0; k < 3; k++)
            for (int k2 = 0; k2 < 3; k2++) {
                float s = 0.f;
                for (int f = 0; f < 3; f++) s += o[f][k] * o[f][k2];
                M[i][k][k2] = s;
            }
    }

    // u = R @ (10*[sin t, cos t, sin t])
    float t  = t_p[0];
    float st = sinf(t), ct = cosf(t);
    float base[3] = {10.f * st, 10.f * ct, 10.f * st};
    float u[3];
    for (int k = 0; k < 3; k++) {
        float s = 0.f;
        for (int j = 0; j < 3; j++) s += R[k * 3 + j] * base[j];
        u[k] = s;
    }

    // channel-collapse scalars for both branches
    float alpha1 = 0.f, beta1 = 0.f, alpha2 = 0.f, beta2 = 0.f;
    for (int f = 0; f < F; f++) {
        float s1 = 0.f, s2 = 0.f;
        for (int g = 0; g < F; g++) {
            s1 += Wb1_d1[f * F + g] * Wb1_lin[g];
            s2 += Wb1_d2[f * F + g] * Wb1_lin[g];
        }
        alpha1 += Wout[f] * s1 * s2;
        beta1  += Wout[f] * Wb1_lin[f];
    }
    for (int f = 0; f < F; f++) {
        float s1 = 0.f, s2 = 0.f;
        for (int g = 0; g < F; g++) {
            s1 += Wb2_d1[f * F + g] * Wb2_lin[g];
            s2 += Wb2_d2[f * F + g] * Wb2_lin[g];
        }
        alpha2 += Wout[f] * s1 * s2;
        beta2  += Wout[f] * Wb2_lin[f];
    }

    // constant u-branch vector: v0 = alpha2 * cross(M3 u, M4 u) + beta2 * u
    float y3[3], y4[3];
    for (int k = 0; k < 3; k++) {
        float s3 = 0.f, s4 = 0.f;
        for (int j = 0; j < 3; j++) { s3 += M[2][k][j] * u[j]; s4 += M[3][k][j] * u[j]; }
        y3[k] = s3; y4[k] = s4;
    }
    float cru[3] = { y3[1] * y4[2] - y3[2] * y4[1],
                     y3[2] * y4[0] - y3[0] * y4[2],
                     y3[0] * y4[1] - y3[1] * y4[0] };
    for (int k = 0; k < 3; k++) g_c.v0[k] = alpha2 * cru[k] + beta2 * u[k];
    g_c.beta = beta1;

    // quadratic forms: out_k quad part = alpha1 * eps_{k p q} (M1 x)_p (M2 x)_q
    for (int k = 0; k < 3; k++) {
        int k1 = (k + 1) % 3, k2 = (k + 2) % 3;
        float Q[3][3];
        for (int ii = 0; ii < 3; ii++)
            for (int jj = 0; jj < 3; jj++)
                Q[ii][jj] = alpha1 * (M[0][k1][ii] * M[1][k2][jj]
                                      - M[0][k2][ii] * M[1][k1][jj]);
        g_c.S[k][0] = Q[0][0];
        g_c.S[k][1] = Q[1][1];
        g_c.S[k][2] = Q[2][2];
        g_c.S[k][3] = Q[0][1] + Q[1][0];
        g_c.S[k][4] = Q[0][2] + Q[2][0];
        g_c.S[k][5] = Q[1][2] + Q[2][1];
    }
}

__device__ __forceinline__ void eval3(const float* __restrict__ c,
                                      float x0, float x1, float x2,
                                      float& o0, float& o1, float& o2)
{
    float p0 = x0 * x0, p1 = x1 * x1, p2 = x2 * x2;
    float p3 = x0 * x1, p4 = x0 * x2, p5 = x1 * x2;
    float beta = c[18];
    o0 = c[19] + beta * x0 + c[0]  * p0 + c[1]  * p1 + c[2]  * p2 + c[3]  * p3 + c[4]  * p4 + c[5]  * p5;
    o1 = c[20] + beta * x1 + c[6]  * p0 + c[7]  * p1 + c[8]  * p2 + c[9]  * p3 + c[10] * p4 + c[11] * p5;
    o2 = c[21] + beta * x2 + c[12] * p0 + c[13] * p1 + c[14] * p2 + c[15] * p3 + c[16] * p4 + c[17] * p5;
}

// 4 elements (12 floats = 3 float4) per thread, fully coalesced streaming.
__global__ void apply_kernel(const float* __restrict__ xin,
                             float* __restrict__ out, int B)
{
    float c[22];
    const float* g = (const float*)&g_c;
#pragma unroll
    for (int i = 0; i < 22; i++) c[i] = __ldg(g + i);

    int nq = B >> 2;           // groups of 4 elements
    int i  = blockIdx.x * blockDim.x + threadIdx.x;

    if (i < nq) {
        const float4* in4  = (const float4*)xin;
        float4*       out4 = (float4*)out;
        float4 a = in4[3 * i + 0];
        float4 b = in4[3 * i + 1];
        float4 d = in4[3 * i + 2];

        float r0, r1, r2, r3, r4, r5, r6, r7, r8, r9, r10, r11;
        eval3(c, a.x, a.y, a.z, r0, r1, r2);
        eval3(c, a.w, b.x, b.y, r3, r4, r5);
        eval3(c, b.z, b.w, d.x, r6, r7, r8);
        eval3(c, d.y, d.z, d.w, r9, r10, r11);

        out4[3 * i + 0] = make_float4(r0, r1, r2, r3);
        out4[3 * i + 1] = make_float4(r4, r5, r6, r7);
        out4[3 * i + 2] = make_float4(r8, r9, r10, r11);
    }

    // tail (B not divisible by 4): one extra thread at index nq handles it
    if (i == nq) {
        for (int e = 4 * nq; e < B; e++) {
            float o0, o1, o2;
            eval3(c, xin[3 * e + 0], xin[3 * e + 1], xin[3 * e + 2], o0, o1, o2);
            out[3 * e + 0] = o0;
            out[3 * e + 1] = o1;
            out[3 * e + 2] = o2;
        }
    }
}

extern "C" void kernel_launch(void* const* d_in, const int* in_sizes, int n_in,
                              void* d_out, int out_size)
{
    const float* t_p     = (const float*)d_in[0];
    const float* x       = (const float*)d_in[1];
    const float* R       = (const float*)d_in[2];
    const float* m       = (const float*)d_in[3];
    const float* Wl1     = (const float*)d_in[4];
    const float* Wd1     = (const float*)d_in[5];
    const float* Wl2     = (const float*)d_in[6];
    const float* Wd2     = (const float*)d_in[7];
    const float* Wl3     = (const float*)d_in[8];
    const float* Wd3     = (const float*)d_in[9];
    const float* Wl4     = (const float*)d_in[10];
    const float* Wd4     = (const float*)d_in[11];
    const float* Wb1_lin = (const float*)d_in[12];
    const float* Wb1_d1  = (const float*)d_in[13];
    const float* Wb1_d2  = (const float*)d_in[14];
    const float* Wb2_lin = (const float*)d_in[15];
    const float* Wb2_d1  = (const float*)d_in[16];
    const float* Wb2_d2  = (const float*)d_in[17];
    const float* Wout    = (const float*)d_in[18];

    int B = in_sizes[1] / 3;

    setup_kernel<<<1, 32>>>(t_p, R, m, Wl1, Wd1, Wl2, Wd2, Wl3, Wd3, Wl4, Wd4,
                            Wb1_lin, Wb1_d1, Wb1_d2, Wb2_lin, Wb2_d1, Wb2_d2, Wout);

    int nq      = B >> 2;
    int threads = nq + 1;          // +1 thread for the tail
    int block   = 256;
    int grid    = (threads + block - 1) / block;
    apply_kernel<<<grid, block>>>(x, (float*)d_out, B);
}

// round 2
// speedup vs baseline: 1.8616x; 1.8616x over previous
#include <cuda_runtime.h>
#include <math.h>

// out_b[k] = p(x_b) . S[k] + beta * x_b[k] + v0[k]
// p(x) = (x0^2, x1^2, x2^2, x0x1, x0x2, x1x2)
// Flat layout: c[0..17]=S, c[18]=beta, c[19..21]=v0, c[22..23]=pad
struct alignas(16) Consts { float c[24]; };
__device__ Consts g_c;

__global__ void setup_kernel(const float* __restrict__ t_p,
                             const float* __restrict__ R,
                             const float* __restrict__ m,
                             const float* __restrict__ Wl1, const float* __restrict__ Wd1,
                             const float* __restrict__ Wl2, const float* __restrict__ Wd2,
                             const float* __restrict__ Wl3, const float* __restrict__ Wd3,
                             const float* __restrict__ Wl4, const float* __restrict__ Wd4,
                             const float* __restrict__ Wb1_lin,
                             const float* __restrict__ Wb1_d1, const float* __restrict__ Wb1_d2,
                             const float* __restrict__ Wb2_lin,
                             const float* __restrict__ Wb2_d1, const float* __restrict__ Wb2_d2,
                             const float* __restrict__ Wout)
{
    const int F = 20;
    int lane = threadIdx.x;

    __shared__ float mm_s[20][3];
    __shared__ float M_s[4][3][3];

    // ---- Phase A: mm[f][k] = sum_j R[k][j] * m[j][f]   (20 lanes) ----
    if (lane < F) {
        float m0 = m[0 * F + lane], m1 = m[1 * F + lane], m2 = m[2 * F + lane];
#pragma unroll
        for (int k = 0; k < 3; k++)
            mm_s[lane][k] = fmaf(R[k * 3 + 0], m0, fmaf(R[k * 3 + 1], m1, R[k * 3 + 2] * m2));
    }

    // ---- Phase B: channel-collapse scalars (20 lanes, warp reduce) ----
    // alpha = sum_f Wout[f] * (Wd1@lin)[f] * (Wd2@lin)[f];  beta = sum_f Wout[f]*lin[f]
    float a1 = 0.f, b1 = 0.f, a2 = 0.f, b2 = 0.f;
    if (lane < F) {
        float s11 = 0.f, s12 = 0.f, s21 = 0.f, s22 = 0.f;
#pragma unroll 4
        for (int g = 0; g < F; g++) {
            float l1 = Wb1_lin[g], l2 = Wb2_lin[g];
            s11 = fmaf(Wb1_d1[lane * F + g], l1, s11);
            s12 = fmaf(Wb1_d2[lane * F + g], l1, s12);
            s21 = fmaf(Wb2_d1[lane * F + g], l2, s21);
            s22 = fmaf(Wb2_d2[lane * F + g], l2, s22);
        }
        float wo = Wout[lane];
        a1 = wo * s11 * s12;
        b1 = wo * Wb1_lin[lane];
        a2 = wo * s21 * s22;
        b2 = wo * Wb2_lin[lane];
    }
#pragma unroll
    for (int off = 16; off > 0; off >>= 1) {
        a1 += __shfl_down_sync(0xffffffffu, a1, off);
        b1 += __shfl_down_sync(0xffffffffu, b1, off);
        a2 += __shfl_down_sync(0xffffffffu, a2, off);
        b2 += __shfl_down_sync(0xffffffffu, b2, off);
    }
    __syncwarp();

    // ---- Phase C: map_m chains -> M[i] (4 lanes, needs mm_s) ----
    if (lane < 4) {
        const float* Wls[4] = {Wl1, Wl2, Wl3, Wl4};
        const float* Wds[4] = {Wd1, Wd2, Wd3, Wd4};
        const float* Wl = Wls[lane];
        const float* Wd = Wds[lane];
        float y0[3][3], d[3][3], o[3][3];
#pragma unroll
        for (int a = 0; a < 3; a++)
#pragma unroll
            for (int k = 0; k < 3; k++) {
                float s = 0.f;
                for (int f = 0; f < F; f++) s = fmaf(Wl[a * F + f], mm_s[f][k], s);
                y0[a][k] = s;
            }
#pragma unroll
        for (int p = 0; p < 3; p++)
#pragma unroll
            for (int k = 0; k < 3; k++)
                d[p][k] = fmaf(Wd[p * 3 + 0], y0[0][k],
                          fmaf(Wd[p * 3 + 1], y0[1][k], Wd[p * 3 + 2] * y0[2][k]));
#pragma unroll
        for (int f = 0; f < 3; f++) {
            float xd = 0.f, dd = 0.f;
#pragma unroll
            for (int k = 0; k < 3; k++) { xd = fmaf(y0[f][k], d[f][k], xd); dd = fmaf(d[f][k], d[f][k], dd); }
            float kf_xd = -2.f * xd;
            float kf_dd = -2.f * dd;
            float denom = fminf(kf_dd, -1e-12f);
            float coef  = (kf_xd < 0.f) ? 0.f : (kf_xd / denom);
#pragma unroll
            for (int k = 0; k < 3; k++) o[f][k] = fmaf(-coef, d[f][k], y0[f][k]);
        }
#pragma unroll
        for (int k = 0; k < 3; k++)
#pragma unroll
            for (int k2 = 0; k2 < 3; k2++)
                M_s[lane][k][k2] = fmaf(o[0][k], o[0][k2],
                                   fmaf(o[1][k], o[1][k2], o[2][k] * o[2][k2]));
    }
    __syncwarp();

    // ---- Phase D: final assembly (lane 0 holds reduced a1/b1/a2/b2) ----
    if (lane == 0) {
        float t  = t_p[0];
        float st = sinf(t), ct = cosf(t);
        float base[3] = {10.f * st, 10.f * ct, 10.f * st};
        float u[3];
#pragma unroll
        for (int k = 0; k < 3; k++)
            u[k] = fmaf(R[k * 3 + 0], base[0], fmaf(R[k * 3 + 1], base[1], R[k * 3 + 2] * base[2]));

        float y3[3], y4[3];
#pragma unroll
        for (int k = 0; k < 3; k++) {
            y3[k] = fmaf(M_s[2][k][0], u[0], fmaf(M_s[2][k][1], u[1], M_s[2][k][2] * u[2]));
            y4[k] = fmaf(M_s[3][k][0], u[0], fmaf(M_s[3][k][1], u[1], M_s[3][k][2] * u[2]));
        }
        float cru0 = y3[1] * y4[2] - y3[2] * y4[1];
        float cru1 = y3[2] * y4[0] - y3[0] * y4[2];
        float cru2 = y3[0] * y4[1] - y3[1] * y4[0];

        g_c.c[18] = b1;
        g_c.c[19] = fmaf(a2, cru0, b2 * u[0]);
        g_c.c[20] = fmaf(a2, cru1, b2 * u[1]);
        g_c.c[21] = fmaf(a2, cru2, b2 * u[2]);
        g_c.c[22] = 0.f; g_c.c[23] = 0.f;

#pragma unroll
        for (int k = 0; k < 3; k++) {
            int k1 = (k + 1) % 3, k2 = (k + 2) % 3;
            float Q[3][3];
#pragma unroll
            for (int ii = 0; ii < 3; ii++)
#pragma unroll
                for (int jj = 0; jj < 3; jj++)
                    Q[ii][jj] = a1 * (M_s[0][k1][ii] * M_s[1][k2][jj]
                                      - M_s[0][k2][ii] * M_s[1][k1][jj]);
            g_c.c[k * 6 + 0] = Q[0][0];
            g_c.c[k * 6 + 1] = Q[1][1];
            g_c.c[k * 6 + 2] = Q[2][2];
            g_c.c[k * 6 + 3] = Q[0][1] + Q[1][0];
            g_c.c[k * 6 + 4] = Q[0][2] + Q[2][0];
            g_c.c[k * 6 + 5] = Q[1][2] + Q[2][1];
        }
    }
}

__device__ __forceinline__ void eval3(const float* __restrict__ c,
                                      float x0, float x1, float x2,
                                      float& o0, float& o1, float& o2)
{
    float p0 = x0 * x0, p1 = x1 * x1, p2 = x2 * x2;
    float p3 = x0 * x1, p4 = x0 * x2, p5 = x1 * x2;
    float beta = c[18];
    o0 = fmaf(c[0],  p0, fmaf(c[1],  p1, fmaf(c[2],  p2, fmaf(c[3],  p3, fmaf(c[4],  p4, fmaf(c[5],  p5, fmaf(beta, x0, c[19])))))));
    o1 = fmaf(c[6],  p0, fmaf(c[7],  p1, fmaf(c[8],  p2, fmaf(c[9],  p3, fmaf(c[10], p4, fmaf(c[11], p5, fmaf(beta, x1, c[20])))))));
    o2 = fmaf(c[12], p0, fmaf(c[13], p1, fmaf(c[14], p2, fmaf(c[15], p3, fmaf(c[16], p4, fmaf(c[17], p5, fmaf(beta, x2, c[21])))))));
}

// 8 elements (24 floats = 6 float4) per thread, fully coalesced streaming.
__global__ void apply_kernel(const float* __restrict__ xin,
                             float* __restrict__ out, int B)
{
    // Load the 24 constants as 6 float4 (L2-broadcast hits).
    union { float4 v4[6]; float f[24]; } cu;
    const float4* cp = (const float4*)&g_c;
#pragma unroll
    for (int j = 0; j < 6; j++) cu.v4[j] = __ldg(cp + j);
    const float* c = cu.f;

    int n8 = B >> 3;            // groups of 8 elements
    int i  = blockIdx.x * blockDim.x + threadIdx.x;

    if (i < n8) {
        const float4* in4  = (const float4*)xin;
        float4*       out4 = (float4*)out;
        float4 v[6];
#pragma unroll
        for (int j = 0; j < 6; j++) v[j] = in4[6 * i + j];

        const float* xf = (const float*)v;
        float r[24];
#pragma unroll
        for (int e = 0; e < 8; e++)
            eval3(c, xf[3 * e + 0], xf[3 * e + 1], xf[3 * e + 2],
                  r[3 * e + 0], r[3 * e + 1], r[3 * e + 2]);

        const float4* rv = (const float4*)r;
#pragma unroll
        for (int j = 0; j < 6; j++) out4[6 * i + j] = rv[j];
    }

    // tail (B not divisible by 8): one extra thread handles it
    if (i == n8) {
        for (int e = 8 * n8; e < B; e++) {
            float o0, o1, o2;
            eval3(c, xin[3 * e + 0], xin[3 * e + 1], xin[3 * e + 2], o0, o1, o2);
            out[3 * e + 0] = o0;
            out[3 * e + 1] = o1;
            out[3 * e + 2] = o2;
        }
    }
}

extern "C" void kernel_launch(void* const* d_in, const int* in_sizes, int n_in,
                              void* d_out, int out_size)
{
    const float* t_p     = (const float*)d_in[0];
    const float* x       = (const float*)d_in[1];
    const float* R       = (const float*)d_in[2];
    const float* m       = (const float*)d_in[3];
    const float* Wl1     = (const float*)d_in[4];
    const float* Wd1     = (const float*)d_in[5];
    const float* Wl2     = (const float*)d_in[6];
    const float* Wd2     = (const float*)d_in[7];
    const float* Wl3     = (const float*)d_in[8];
    const float* Wd3     = (const float*)d_in[9];
    const float* Wl4     = (const float*)d_in[10];
    const float* Wd4     = (const float*)d_in[11];
    const float* Wb1_lin = (const float*)d_in[12];
    const float* Wb1_d1  = (const float*)d_in[13];
    const float* Wb1_d2  = (const float*)d_in[14];
    const float* Wb2_lin = (const float*)d_in[15];
    const float* Wb2_d1  = (const float*)d_in[16];
    const float* Wb2_d2  = (const float*)d_in[17];
    const float* Wout    = (const float*)d_in[18];

    int B = in_sizes[1] / 3;

    setup_kernel<<<1, 32>>>(t_p, R, m, Wl1, Wd1, Wl2, Wd2, Wl3, Wd3, Wl4, Wd4,
                            Wb1_lin, Wb1_d1, Wb1_d2, Wb2_lin, Wb2_d1, Wb2_d2, Wout);

    int n8      = B >> 3;
    int threads = n8 + 1;          // +1 thread for the tail
    int block   = 256;
    int grid    = (threads + block - 1) / block;
    apply_kernel<<<grid, block>>>(x, (float*)d_out, B);
}